// round 1
// baseline (speedup 1.0000x reference)
#include <cuda_runtime.h>

// CritiGraph_64175401337324 — full pipeline, one CTA per t.
// T=1024, S=64, D=256, TP=8, H=16, N_K=2, C=65, CUR_TP=4, CUR_PORTION=0.8

namespace {
constexpr int T_   = 1024;
constexpr int S_   = 64;
constexpr int D_   = 256;
constexpr int TP_  = 8;
constexpr int H_   = 16;
constexpr int NK_  = 2;
constexpr int C_   = 2 * H_ * NK_ + 1;   // 65
constexpr int CUR_TP_ = 4;
}

// 1 if integer inputs are int64, 0 if int32 (JAX without x64 downcasts).
__device__ int g_is64;

__global__ void detect_dtype_kernel(const void* p0) {
    // If the buffer really holds int64 values in [-65535, 65535], every
    // 8-byte word has its high 32 bits equal to the sign extension of the
    // low 32 bits. For int32 data this holds with probability ~1/131071
    // per word — 64 words make misdetection impossible in practice.
    const long long* p = (const long long*)p0;
    int ok = 1;
    for (int i = 0; i < 64; ++i) {
        long long v = p[i];
        int lo = (int)v;
        int hi = (int)(v >> 32);
        if (hi != (lo < 0 ? -1 : 0)) { ok = 0; break; }
    }
    g_is64 = ok;
}

__device__ __forceinline__ int load_i(const void* p, int idx, int is64) {
    if (is64) return (int)((const long long*)p)[idx];
    return ((const int*)p)[idx];
}

// pack |v| (<= 65536, 17 bits) with sign in bit 31
__device__ __forceinline__ unsigned enc_loc(int v) {
    unsigned a = (unsigned)(v < 0 ? -v : v);
    if (v < 0) a |= 0x80000000u;
    return a;
}

// returns sign * (16 - e) as float, where e = frexp-exponent of (|a|^|b|)+1.
// Caller multiplies by 1/16 (cos value) or 1/128 (cos/TP). Exact in fp32.
__device__ __forceinline__ float cos_core(unsigned ea, unsigned eb) {
    unsigned u = ea ^ eb;                       // bit31 = sign differ, low = abs xor
    int e = 32 - __clz((int)((u & 0x7FFFFFFFu) + 1u));
    float f = (float)(16 - e);
    return (u & 0x80000000u) ? -f : f;
}

__global__ void __launch_bounds__(256, 1) critigraph_kernel(
    const void* __restrict__ sta_loc,
    const void* __restrict__ nei_loc,
    const void* __restrict__ rand_numbers,
    const float* __restrict__ sta_emb,
    const float* __restrict__ nei_emb,
    const float* __restrict__ mask,
    const float* __restrict__ rand_vals,
    const float* __restrict__ t_rand,
    float* __restrict__ out)
{
    const int t    = blockIdx.x;
    const int tid  = threadIdx.x;
    const int lane = tid & 31;
    const int warp = tid >> 5;
    const int is64 = g_is64;

    __shared__ __align__(16) float s_sta[D_];
    __shared__ float    s_eu[S_];
    __shared__ float    s_w[S_];            // mask, later |eu|*mask
    __shared__ float    s_A8[S_][TP_];      // (cos_sn_sum - cos_sn) / 8
    __shared__ unsigned s_nl[S_][TP_];      // encoded nei_loc
    __shared__ unsigned s_cl[C_][TP_];      // encoded cnc_loc
    __shared__ int      s_clv[C_][TP_];     // raw cnc_loc values
    __shared__ float    s_loss[C_][TP_];    // temp cos_sn, then final loss
    __shared__ float    s_red[8];
    __shared__ float    s_ss, s_lth;
    __shared__ int      s_ori[TP_];

    // ---- phase 1: load sta_emb row, mask, sta_loc; reduce ||sta||^2, lth
    float x = sta_emb[t * D_ + tid];
    s_sta[tid] = x;
    float p2 = x * x;
    #pragma unroll
    for (int off = 16; off; off >>= 1) p2 += __shfl_xor_sync(0xFFFFFFFFu, p2, off);
    if (lane == 0) s_red[warp] = p2;
    if (tid < S_)  s_w[tid] = mask[t * S_ + tid];
    if (tid < TP_) s_ori[tid] = load_i(sta_loc, t * TP_ + tid, is64);
    __syncthreads();
    if (tid == 0) {
        float ss = 0.f;
        #pragma unroll
        for (int i = 0; i < 8; ++i) ss += s_red[i];
        s_ss = ss;
        float l = 0.f;
        for (int s = 0; s < S_; ++s) l += s_w[s];
        s_lth = l + 1e-12f;
    }
    __syncthreads();

    // ---- phase 2a: eu[s] = cos similarity of embeddings (warp per 8 s)
    {
        const float sqss = sqrtf(s_ss);
        const float4* sta4 = (const float4*)s_sta;
        float4 ua = sta4[lane];
        float4 ub = sta4[lane + 32];
        #pragma unroll
        for (int i = 0; i < 8; ++i) {
            int s = (warp << 3) + i;
            const float4* nb4 = (const float4*)(nei_emb + ((size_t)(t * S_ + s)) * D_);
            float4 a = nb4[lane];
            float4 b = nb4[lane + 32];
            float dot = a.x*ua.x + a.y*ua.y + a.z*ua.z + a.w*ua.w
                      + b.x*ub.x + b.y*ub.y + b.z*ub.z + b.w*ub.w;
            float nn  = a.x*a.x + a.y*a.y + a.z*a.z + a.w*a.w
                      + b.x*b.x + b.y*b.y + b.z*b.z + b.w*b.w;
            #pragma unroll
            for (int off = 16; off; off >>= 1) {
                dot += __shfl_xor_sync(0xFFFFFFFFu, dot, off);
                nn  += __shfl_xor_sync(0xFFFFFFFFu, nn, off);
            }
            if (lane == 0) {
                float eu = dot / (sqss * sqrtf(nn));
                s_eu[s] = eu;
                s_w[s]  = fabsf(eu) * s_w[s];   // |eu| * mask
            }
        }
    }

    // ---- phase 2b: encode nei_loc + cos_sn (into s_loss temp)
    for (int q = tid; q < S_ * TP_; q += 256) {
        int s = q >> 3, p = q & 7;
        int nl = load_i(nei_loc, (t * S_ + s) * TP_ + p, is64);
        unsigned ne = enc_loc(nl);
        s_nl[s][p] = ne;
        s_loss[s][p] = cos_core(enc_loc(s_ori[p]), ne) * 0.0625f;  // exact
    }

    // ---- phase 2c: connection candidates
    for (int q = tid; q < C_ * TP_; q += 256) {
        int c = q >> 3, p = q & 7;
        int ori = s_ori[p];
        int v;
        if (c == 32) {
            v = ori;
        } else {
            int cc = (c < 32) ? c : (c - 33);
            int h = cc >> 1, j = cc & 1;
            int rn = load_i(rand_numbers, ((t * H_ + h) * NK_ + j) * TP_ + p, is64);
            v = (ori ^ (1 << h)) ^ (rn & ((1 << h) - 1));
            if (c > 32) v = -v;
        }
        s_clv[c][p] = v;
        s_cl[c][p]  = enc_loc(v);
    }
    __syncthreads();

    // ---- phase 3: A8[s][p] = (cos_sn_sum - cos_sn) / 8 (all exact fp32)
    for (int q = tid; q < S_ * TP_; q += 256) {
        int s = q >> 3, p = q & 7;
        float sum = 0.f;
        #pragma unroll
        for (int pp = 0; pp < TP_; ++pp) sum += s_loss[s][pp];
        s_A8[s][p] = (sum - s_loss[s][p]) * 0.125f;
    }
    __syncthreads();

    // ---- phase 4: per-candidate loss. Each thread does (c, p) and (c+32, p),
    // sharing the per-s shared loads between the two candidates.
    const float lth = s_lth;
    {
        int p  = tid & 7;
        int c0 = tid >> 3;                     // 0..31
        unsigned e0 = s_cl[c0][p];
        unsigned e1 = s_cl[c0 + 32][p];
        float acc0 = 0.f, acc1 = 0.f;
        #pragma unroll 4
        for (int s = 0; s < S_; ++s) {
            unsigned ne = s_nl[s][p];
            float A8 = s_A8[s][p];
            float eu = s_eu[s];
            float w  = s_w[s];
            float v0 = cos_core(e0, ne) * 0.0078125f;          // cos/8, exact
            float d0 = __fsub_rn(__fadd_rn(A8, v0), eu);       // matches ref rounding
            acc0 = __fadd_rn(acc0, __fmul_rn(__fmul_rn(d0, d0), w));
            float v1 = cos_core(e1, ne) * 0.0078125f;
            float d1 = __fsub_rn(__fadd_rn(A8, v1), eu);
            acc1 = __fadd_rn(acc1, __fmul_rn(__fmul_rn(d1, d1), w));
        }
        s_loss[c0][p]      = __fdiv_rn(acc0, lth);
        s_loss[c0 + 32][p] = __fdiv_rn(acc1, lth);
    }
    if (tid < TP_) {                            // candidate c = 64
        int p = tid;
        unsigned e = s_cl[64][p];
        float acc = 0.f;
        #pragma unroll 4
        for (int s = 0; s < S_; ++s) {
            unsigned ne = s_nl[s][p];
            float v = cos_core(e, ne) * 0.0078125f;
            float d = __fsub_rn(__fadd_rn(s_A8[s][p], v), s_eu[s]);
            acc = __fadd_rn(acc, __fmul_rn(__fmul_rn(d, d), s_w[p == p ? s : s]));
        }
        s_loss[64][p] = __fdiv_rn(acc, lth);
    }
    __syncthreads();

    // ---- phase 5: argmin, selection, outputs (trivial; one thread)
    if (tid == 0) {
        float rv[TP_];
        #pragma unroll
        for (int p = 0; p < TP_; ++p) rv[p] = rand_vals[t * TP_ + p];
        bool sel = t_rand[t] < 0.8f;
        float rlsum = 0.f;
        for (int p = 0; p < TP_; ++p) {
            // strict-< ascending argmin -> first index on exact ties (matches jnp)
            float best = s_loss[0][p];
            int bc = 0;
            for (int c = 1; c < C_; ++c) {
                float v = s_loss[c][p];
                if (v < best) { best = v; bc = c; }
            }
            // stable rank of rand_vals[p]; selected iff among 4 smallest
            int rank = 0;
            #pragma unroll
            for (int q = 0; q < TP_; ++q)
                rank += (rv[q] < rv[p]) || (rv[q] == rv[p] && q < p);
            int idx = (rank < CUR_TP_ && sel) ? bc : 32;
            out[t * TP_ + p] = (float)s_clv[idx][p];
            rlsum = __fadd_rn(rlsum, s_loss[idx][p]);
        }
        out[T_ * TP_ + t] = rlsum * 0.125f;     // mean over TP
    }
}

extern "C" void kernel_launch(void* const* d_in, const int* in_sizes, int n_in,
                              void* d_out, int out_size) {
    (void)in_sizes; (void)n_in; (void)out_size;
    detect_dtype_kernel<<<1, 1>>>(d_in[0]);
    critigraph_kernel<<<T_, 256>>>(
        d_in[0], d_in[1], d_in[2],
        (const float*)d_in[3], (const float*)d_in[4], (const float*)d_in[5],
        (const float*)d_in[6], (const float*)d_in[7],
        (float*)d_out);
}

// round 2
// speedup vs baseline: 1.2209x; 1.2209x over previous
#include <cuda_runtime.h>

// CritiGraph_64175401337324 — two-kernel split:
//   A: streaming eu = cos(sta_emb, nei_emb) with deep MLP  (DRAM-bound, ~64MB)
//   B: integer cos-sim loss / argmin / selection            (issue-bound)
// T=1024, S=64, D=256, TP=8, H=16, N_K=2, C=65, CUR_TP=4, CUR_PORTION=0.8

namespace {
constexpr int T_   = 1024;
constexpr int S_   = 64;
constexpr int D_   = 256;
constexpr int TP_  = 8;
constexpr int H_   = 16;
constexpr int NK_  = 2;
constexpr int C_   = 2 * H_ * NK_ + 1;   // 65
constexpr int CUR_TP_ = 4;
}

__device__ int   g_is64;
__device__ float g_eu[T_ * S_];          // 256 KB scratch (static, allowed)

__device__ __forceinline__ int load_i(const void* p, int idx, int is64) {
    if (is64) return (int)((const long long*)p)[idx];
    return ((const int*)p)[idx];
}

// pack |v| with sign in bit 31
__device__ __forceinline__ unsigned enc_loc(int v) {
    unsigned a = (unsigned)(v < 0 ? -v : v);
    if (v < 0) a |= 0x80000000u;
    return a;
}

// sign * (16 - e), e = frexp-exponent of ((|a|^|b|)+1). Exact in fp32.
__device__ __forceinline__ float cos_core(unsigned ea, unsigned eb) {
    unsigned u = ea ^ eb;
    int e = 32 - __clz((int)((u & 0x7FFFFFFFu) + 1u));
    float f = (float)(16 - e);
    return (u & 0x80000000u) ? -f : f;
}

// ---------------------------------------------------------------------------
// Kernel A: eu[t][s] = dot(sta,nei) / (||sta|| * ||nei||)
// grid = T*4, block = 128 (4 warps), each warp handles 4 s-rows.
// 8 LDG.128 per lane in flight per warp -> high MLP, DRAM-saturating.
// ---------------------------------------------------------------------------
__global__ void __launch_bounds__(128, 1) eu_kernel(
    const float* __restrict__ sta_emb,
    const float* __restrict__ nei_emb,
    const void*  __restrict__ sta_loc_probe)
{
    // int32/int64 dtype detection (once, by one thread; visible to kernel B
    // across the kernel boundary). Int64 in [-131071,131071] => every 8-byte
    // word's high half is the sign extension of the low half.
    if (blockIdx.x == 0 && threadIdx.x == 0) {
        const long long* p = (const long long*)sta_loc_probe;
        int ok = 1;
        for (int i = 0; i < 64; ++i) {
            long long v = p[i];
            int lo = (int)v, hi = (int)(v >> 32);
            if (hi != (lo < 0 ? -1 : 0)) { ok = 0; break; }
        }
        g_is64 = ok;
    }

    const int t    = blockIdx.x >> 2;
    const int quad = blockIdx.x & 3;
    const int tid  = threadIdx.x;
    const int lane = tid & 31;
    const int warp = tid >> 5;

    __shared__ __align__(16) float s_sta[D_];
    __shared__ float s_red[4];
    __shared__ float s_sq;

    float x0 = sta_emb[t * D_ + tid];
    float x1 = sta_emb[t * D_ + 128 + tid];
    s_sta[tid]       = x0;
    s_sta[tid + 128] = x1;
    float p2 = x0 * x0 + x1 * x1;
    #pragma unroll
    for (int off = 16; off; off >>= 1) p2 += __shfl_xor_sync(0xFFFFFFFFu, p2, off);
    if (lane == 0) s_red[warp] = p2;
    __syncthreads();
    if (tid == 0) s_sq = sqrtf(s_red[0] + s_red[1] + s_red[2] + s_red[3]);
    __syncthreads();

    const float sqss = s_sq;
    const float4* st4 = (const float4*)s_sta;
    const float4 ua = st4[lane];
    const float4 ub = st4[lane + 32];

    const int sbase = quad * 16 + warp * 4;
    const float4* base = (const float4*)(nei_emb + ((size_t)(t * S_ + sbase)) * D_);

    // preload 4 rows (8 LDG.128 per lane in flight)
    float4 a[4], b[4];
    #pragma unroll
    for (int r = 0; r < 4; ++r) {
        a[r] = base[r * 64 + lane];
        b[r] = base[r * 64 + lane + 32];
    }

    float dot[4], nn[4];
    #pragma unroll
    for (int r = 0; r < 4; ++r) {
        dot[r] = a[r].x*ua.x + a[r].y*ua.y + a[r].z*ua.z + a[r].w*ua.w
               + b[r].x*ub.x + b[r].y*ub.y + b[r].z*ub.z + b[r].w*ub.w;
        nn[r]  = a[r].x*a[r].x + a[r].y*a[r].y + a[r].z*a[r].z + a[r].w*a[r].w
               + b[r].x*b[r].x + b[r].y*b[r].y + b[r].z*b[r].z + b[r].w*b[r].w;
    }
    #pragma unroll
    for (int off = 16; off; off >>= 1) {
        #pragma unroll
        for (int r = 0; r < 4; ++r) {
            dot[r] += __shfl_xor_sync(0xFFFFFFFFu, dot[r], off);
            nn[r]  += __shfl_xor_sync(0xFFFFFFFFu, nn[r],  off);
        }
    }
    if (lane == 0) {
        #pragma unroll
        for (int r = 0; r < 4; ++r)
            g_eu[t * S_ + sbase + r] = dot[r] / (sqss * sqrtf(nn[r]));
    }
}

// ---------------------------------------------------------------------------
// Kernel B: everything else. One CTA per t, 256 threads.
// Phase 4 exploits cos(-a,b) == -cos(a,b) (exact, sign-bit flip) so one
// cos evaluation serves candidate pair (c, c+33). flipmask handles res==0
// (int -0 == 0 keeps '+' sign in the reference).
// ---------------------------------------------------------------------------
__global__ void __launch_bounds__(256, 1) loss_kernel(
    const void*  __restrict__ sta_loc,
    const void*  __restrict__ nei_loc,
    const void*  __restrict__ rand_numbers,
    const float* __restrict__ mask,
    const float* __restrict__ rand_vals,
    const float* __restrict__ t_rand,
    float* __restrict__ out)
{
    const int t    = blockIdx.x;
    const int tid  = threadIdx.x;
    const int lane = tid & 31;
    const int warp = tid >> 5;
    const int is64 = g_is64;

    __shared__ __align__(16) float    s_eu[S_];
    __shared__ __align__(16) float    s_w[S_];          // |eu| * mask
    __shared__ float    s_cs[S_][TP_];                  // cos_sn / 16
    __shared__ __align__(16) unsigned s_nlT[TP_][68];   // transposed, padded
    __shared__ __align__(16) float    s_A8T[TP_][68];   // (sum - cs)/8, transposed
    __shared__ unsigned s_cl[33 * TP_];                 // enc for c = 0..32
    __shared__ int      s_clv[C_ * TP_];                // raw candidate values
    __shared__ float    s_loss[C_ * TP_];
    __shared__ float    s_red[2];
    __shared__ float    s_lth;
    __shared__ int      s_ori[TP_];

    // ---- phase 1: eu, w, lth, ori
    if (tid < S_) {
        float m  = mask[t * S_ + tid];
        float eu = g_eu[t * S_ + tid];
        s_eu[tid] = eu;
        s_w[tid]  = fabsf(eu) * m;
        float l = m;                       // mask is 0/1: exact in any order
        #pragma unroll
        for (int off = 16; off; off >>= 1) l += __shfl_xor_sync(0xFFFFFFFFu, l, off);
        if (lane == 0) s_red[warp] = l;
    }
    if (tid < TP_) s_ori[tid] = load_i(sta_loc, t * TP_ + tid, is64);
    __syncthreads();
    if (tid == 0) s_lth = s_red[0] + s_red[1] + 1e-12f;

    // ---- phase 2b: nei encodings + cos_sn
    for (int q = tid; q < S_ * TP_; q += 256) {
        int s = q >> 3, p = q & 7;
        int nl = load_i(nei_loc, (t * S_ + s) * TP_ + p, is64);
        unsigned ne = enc_loc(nl);
        s_nlT[p][s] = ne;
        s_cs[s][p]  = cos_core(enc_loc(s_ori[p]), ne) * 0.0625f;   // exact
    }

    // ---- phase 2c: connection candidates
    for (int q = tid; q < C_ * TP_; q += 256) {
        int c = q >> 3, p = q & 7;
        int ori = s_ori[p];
        int v;
        if (c == 32) {
            v = ori;
        } else {
            int cc = (c < 32) ? c : (c - 33);
            int h = cc >> 1, j = cc & 1;
            int rn = load_i(rand_numbers, ((t * H_ + h) * NK_ + j) * TP_ + p, is64);
            v = (ori ^ (1 << h)) ^ (rn & ((1 << h) - 1));
            if (c > 32) v = -v;
        }
        s_clv[c * TP_ + p] = v;
        if (c <= 32) s_cl[c * TP_ + p] = enc_loc(v);
    }
    __syncthreads();

    // ---- phase 3: A8T[p][s] = (cos_sn_sum - cos_sn)/8 (exact)
    for (int q = tid; q < S_ * TP_; q += 256) {
        int s = q >> 3, p = q & 7;
        float sum = 0.f;
        #pragma unroll
        for (int pp = 0; pp < TP_; ++pp) sum += s_cs[s][pp];
        s_A8T[p][s] = (sum - s_cs[s][p]) * 0.125f;
    }
    __syncthreads();

    // ---- phase 4: thread (j,p) computes loss for candidates j and j+33.
    const float lth = s_lth;
    {
        const int p = tid & 7;
        const int j = tid >> 3;                       // 0..31
        const unsigned e0 = s_cl[j * TP_ + p];
        // candidate j+33 is -res: sign flips exactly unless res == 0
        const unsigned flipmask = (e0 != 0u) ? 0x80000000u : 0u;

        const uint4*  neP = (const uint4*) &s_nlT[p][0];
        const float4* a8P = (const float4*)&s_A8T[p][0];
        const float4* euP = (const float4*)s_eu;
        const float4* wP  = (const float4*)s_w;

        float acc0 = 0.f, acc1 = 0.f;

#define PROC(NE, A8, EU, W) do {                                              \
        unsigned u = e0 ^ (NE);                                               \
        int m = __clz((int)((u & 0x7FFFFFFFu) + 1u)) - 16;                    \
        float f = (float)m;                                                   \
        float v0 = __fmul_rn(__uint_as_float(__float_as_uint(f) ^             \
                                             (u & 0x80000000u)), 0.0078125f); \
        float v1 = __uint_as_float(__float_as_uint(v0) ^ flipmask);           \
        float d0 = __fsub_rn(__fadd_rn((A8), v0), (EU));                      \
        float d1 = __fsub_rn(__fadd_rn((A8), v1), (EU));                      \
        acc0 = __fmaf_rn(__fmul_rn(d0, (W)), d0, acc0);                       \
        acc1 = __fmaf_rn(__fmul_rn(d1, (W)), d1, acc1);                       \
    } while (0)

        #pragma unroll 4
        for (int g = 0; g < 16; ++g) {
            uint4  n4 = neP[g];
            float4 A4 = a8P[g];
            float4 E4 = euP[g];
            float4 W4 = wP[g];
            PROC(n4.x, A4.x, E4.x, W4.x);
            PROC(n4.y, A4.y, E4.y, W4.y);
            PROC(n4.z, A4.z, E4.z, W4.z);
            PROC(n4.w, A4.w, E4.w, W4.w);
        }
#undef PROC

        s_loss[j * TP_ + p]        = __fdiv_rn(acc0, lth);
        s_loss[(j + 33) * TP_ + p] = __fdiv_rn(acc1, lth);
    }
    if (tid < TP_) {                                   // candidate c = 32 (ori)
        const int p = tid;
        const unsigned e = s_cl[32 * TP_ + p];
        float acc = 0.f;
        #pragma unroll 4
        for (int s = 0; s < S_; ++s) {
            float v = cos_core(e, s_nlT[p][s]) * 0.0078125f;
            float d = __fsub_rn(__fadd_rn(s_A8T[p][s], v), s_eu[s]);
            acc = __fadd_rn(acc, __fmul_rn(__fmul_rn(d, d), s_w[s]));
        }
        s_loss[32 * TP_ + p] = __fdiv_rn(acc, s_lth);
    }
    __syncthreads();

    // ---- phase 5: argmin, selection, outputs
    if (tid == 0) {
        float rv[TP_];
        #pragma unroll
        for (int p = 0; p < TP_; ++p) rv[p] = rand_vals[t * TP_ + p];
        bool sel = t_rand[t] < 0.8f;
        float rlsum = 0.f;
        for (int p = 0; p < TP_; ++p) {
            float best = s_loss[0 * TP_ + p];
            int bc = 0;
            for (int c = 1; c < C_; ++c) {
                float v = s_loss[c * TP_ + p];
                if (v < best) { best = v; bc = c; }     // first-index ties
            }
            int rank = 0;
            #pragma unroll
            for (int q = 0; q < TP_; ++q)
                rank += (rv[q] < rv[p]) || (rv[q] == rv[p] && q < p);
            int idx = (rank < CUR_TP_ && sel) ? bc : 32;
            out[t * TP_ + p] = (float)s_clv[idx * TP_ + p];
            rlsum = __fadd_rn(rlsum, s_loss[idx * TP_ + p]);
        }
        out[T_ * TP_ + t] = rlsum * 0.125f;
    }
}

extern "C" void kernel_launch(void* const* d_in, const int* in_sizes, int n_in,
                              void* d_out, int out_size) {
    (void)in_sizes; (void)n_in; (void)out_size;
    eu_kernel<<<T_ * 4, 128>>>(
        (const float*)d_in[3], (const float*)d_in[4], d_in[0]);
    loss_kernel<<<T_, 256>>>(
        d_in[0], d_in[1], d_in[2],
        (const float*)d_in[5], (const float*)d_in[6], (const float*)d_in[7],
        (float*)d_out);
}